// round 15
// baseline (speedup 1.0000x reference)
#include <cuda_runtime.h>

// ST-BIF IF neuron, T=16 scan — FINAL.
// Converged configuration after 14 measured rounds:
//   - 8 elems/thread via single 256-bit v8.f32 ld/st (Blackwell LDG/STG.256)
//   - non-volatile load asm => ptxas front-batches loads across the unrolled
//     t-loop (MLP) while each load occupies one L1tex queue slot
//   - .cs streaming policy both directions (zero reuse)
//   - block=128, one-shot CTAs (9408), regs=56 -> ~51% occ (measured optimum;
//     higher occupancy increases cross-CTA L1tex queue contention)
//   - rcp-multiply (exact for qth=0.5), float acc, single select chain
// Measured: 6680 GB/s (84.3% DRAM), ncu-dur 177.4us, rel_err 0.0.

#define T_STEPS 16
#define POS_MAX 7.0f
#define NEG_MIN (-8.0f)

__device__ __forceinline__ void ldg256_cs(const float* p, float* r)
{
    // non-volatile: pure load, compiler may reorder/batch freely
    asm("ld.global.cs.v8.f32 {%0,%1,%2,%3,%4,%5,%6,%7}, [%8];"
        : "=f"(r[0]), "=f"(r[1]), "=f"(r[2]), "=f"(r[3]),
          "=f"(r[4]), "=f"(r[5]), "=f"(r[6]), "=f"(r[7])
        : "l"(p));
}

__device__ __forceinline__ void stg256_cs(float* p, const float* r)
{
    asm volatile(
        "st.global.cs.v8.f32 [%0], {%1,%2,%3,%4,%5,%6,%7,%8};"
        :: "l"(p),
           "f"(r[0]), "f"(r[1]), "f"(r[2]), "f"(r[3]),
           "f"(r[4]), "f"(r[5]), "f"(r[6]), "f"(r[7])
        : "memory");
}

__device__ __forceinline__ void step_elem(float& v, float rcp, float qth,
                                          float& q, float& a)
{
    q += v * rcp;                    // qth = 0.5 -> rcp = 2.0 exact
    bool sp = (q - 1.0f >= 0.0f) && (a < POS_MAX);
    bool ng = (q < 0.0f) && (a > NEG_MIN);
    float cur = sp ? 1.0f : (ng ? -1.0f : 0.0f);
    a += cur;
    q -= cur;
    v = cur * qth;                   // output overwrites input register
}

__global__ void __launch_bounds__(128) ifneuron_kernel(
    const float* __restrict__ x,
    const float* __restrict__ qth_ptr,
    float* __restrict__ out,
    int S)   // spatial size (B*N*D), multiple of 8
{
    int idx = (blockIdx.x * blockDim.x + threadIdx.x) * 8;
    if (idx >= S) return;

    const float qth = __ldg(qth_ptr);
    const float rcp = 1.0f / qth;

    float q[8];
    float a[8];
    #pragma unroll
    for (int i = 0; i < 8; i++) { q[i] = 0.5f; a[i] = 0.0f; }

    #pragma unroll
    for (int t = 0; t < T_STEPS; t++) {
        float v[8];
        ldg256_cs(x + (size_t)t * S + idx, v);

        #pragma unroll
        for (int i = 0; i < 8; i++)
            step_elem(v[i], rcp, qth, q[i], a[i]);

        stg256_cs(out + (size_t)t * S + idx, v);
    }
}

extern "C" void kernel_launch(void* const* d_in, const int* in_sizes, int n_in,
                              void* d_out, int out_size)
{
    const float* x   = (const float*)d_in[0];
    const float* qth = (const float*)d_in[1];
    float* out       = (float*)d_out;

    int total = in_sizes[0];          // T * S
    int S = total / T_STEPS;          // 9,633,792
    int nthreads = S / 8;
    int block = 128;
    int grid = (nthreads + block - 1) / block;

    ifneuron_kernel<<<grid, block>>>(x, qth, out, S);
}

// round 16
// speedup vs baseline: 1.0112x; 1.0112x over previous
#include <cuda_runtime.h>

// ST-BIF IF neuron, T=16 scan. R14 converged config (256-bit v8.f32 ld/st,
// non-volatile load asm, .cs streaming, 8 elems/thread, block=128) with the
// loads routed through the non-coherent read-only path (ld.global.nc.cs):
// input is read-only for the kernel lifetime, and the RO datapath relaxes
// L1tex coherence tracking on the read stream.

#define T_STEPS 16
#define POS_MAX 7.0f
#define NEG_MIN (-8.0f)

__device__ __forceinline__ void ldg256_nc_cs(const float* p, float* r)
{
    // non-volatile: pure read-only load, compiler may reorder/batch freely
    asm("ld.global.nc.cs.v8.f32 {%0,%1,%2,%3,%4,%5,%6,%7}, [%8];"
        : "=f"(r[0]), "=f"(r[1]), "=f"(r[2]), "=f"(r[3]),
          "=f"(r[4]), "=f"(r[5]), "=f"(r[6]), "=f"(r[7])
        : "l"(p));
}

__device__ __forceinline__ void stg256_cs(float* p, const float* r)
{
    asm volatile(
        "st.global.cs.v8.f32 [%0], {%1,%2,%3,%4,%5,%6,%7,%8};"
        :: "l"(p),
           "f"(r[0]), "f"(r[1]), "f"(r[2]), "f"(r[3]),
           "f"(r[4]), "f"(r[5]), "f"(r[6]), "f"(r[7])
        : "memory");
}

__device__ __forceinline__ void step_elem(float& v, float rcp, float qth,
                                          float& q, float& a)
{
    q += v * rcp;                    // qth = 0.5 -> rcp = 2.0 exact
    bool sp = (q - 1.0f >= 0.0f) && (a < POS_MAX);
    bool ng = (q < 0.0f) && (a > NEG_MIN);
    float cur = sp ? 1.0f : (ng ? -1.0f : 0.0f);
    a += cur;
    q -= cur;
    v = cur * qth;                   // output overwrites input register
}

__global__ void __launch_bounds__(128) ifneuron_kernel(
    const float* __restrict__ x,
    const float* __restrict__ qth_ptr,
    float* __restrict__ out,
    int S)   // spatial size (B*N*D), multiple of 8
{
    int idx = (blockIdx.x * blockDim.x + threadIdx.x) * 8;
    if (idx >= S) return;

    const float qth = __ldg(qth_ptr);
    const float rcp = 1.0f / qth;

    float q[8];
    float a[8];
    #pragma unroll
    for (int i = 0; i < 8; i++) { q[i] = 0.5f; a[i] = 0.0f; }

    #pragma unroll
    for (int t = 0; t < T_STEPS; t++) {
        float v[8];
        ldg256_nc_cs(x + (size_t)t * S + idx, v);

        #pragma unroll
        for (int i = 0; i < 8; i++)
            step_elem(v[i], rcp, qth, q[i], a[i]);

        stg256_cs(out + (size_t)t * S + idx, v);
    }
}

extern "C" void kernel_launch(void* const* d_in, const int* in_sizes, int n_in,
                              void* d_out, int out_size)
{
    const float* x   = (const float*)d_in[0];
    const float* qth = (const float*)d_in[1];
    float* out       = (float*)d_out;

    int total = in_sizes[0];          // T * S
    int S = total / T_STEPS;          // 9,633,792
    int nthreads = S / 8;
    int block = 128;
    int grid = (nthreads + block - 1) / block;

    ifneuron_kernel<<<grid, block>>>(x, qth, out, S);
}